// round 9
// baseline (speedup 1.0000x reference)
#include <cuda_runtime.h>
#include <cuda_bf16.h>

// out[i,j] = dot(z1[i], z2[j]) if batch[i]==batch[j] && cls[i]==cls[j]
//            && !(24<=cls[i]<=26) && i!=j, else 0.
//
// Fused single kernel. ONE WAVE: 768 CTAs x 256 threads (196k threads fit in
// the 303k-thread chip capacity; round 8's 1536-CTA grid ran 1.3 waves and
// capped DRAM at 65%). Each warp owns 2 adjacent rows (96KB contiguous fill):
//   phase 1: sparse dots for both rows -> SMEM staging
//   phase 2: zero-fill the 2-row span (pure STG.128 stream, balanced)
//   phase 3: overwrite staged values (SMEM reads only)

#define CAP 64               // staged matches per row (avg ~9.5; tail-safe)
#define ROWS_PER_WARP 2

__device__ __forceinline__ int lower_bound_dev(const int* __restrict__ a, int n, int v) {
    int lo = 0, hi = n;
    while (lo < hi) { int m = (lo + hi) >> 1; if (a[m] < v) lo = m + 1; else hi = m; }
    return lo;
}
__device__ __forceinline__ int upper_bound_dev(const int* __restrict__ a, int n, int v) {
    int lo = 0, hi = n;
    while (lo < hi) { int m = (lo + hi) >> 1; if (a[m] <= v) lo = m + 1; else hi = m; }
    return lo;
}
__device__ __forceinline__ float warp_reduce_add(float d) {
    d += __shfl_xor_sync(0xffffffffu, d, 16);
    d += __shfl_xor_sync(0xffffffffu, d, 8);
    d += __shfl_xor_sync(0xffffffffu, d, 4);
    d += __shfl_xor_sync(0xffffffffu, d, 2);
    d += __shfl_xor_sync(0xffffffffu, d, 1);
    return d;
}

__global__ void __launch_bounds__(256)
fused_onewave_d128(const float* __restrict__ z1,
                   const float* __restrict__ z2,
                   const int*  __restrict__ cls,
                   const int*  __restrict__ batch,
                   float* __restrict__ out,
                   int N)
{
    __shared__ int   scol[8][ROWS_PER_WARP][CAP];
    __shared__ float sval[8][ROWS_PER_WARP][CAP];

    const int lane = threadIdx.x & 31;
    const int w    = threadIdx.x >> 5;
    const int gw   = (blockIdx.x * blockDim.x + threadIdx.x) >> 5;   // global warp
    const int row0 = gw * ROWS_PER_WARP;
    if (row0 >= N) return;

    int kcnt[ROWS_PER_WARP];
    int cls_r[ROWS_PER_WARP];

    // ---------------- phase 1: sparse dots -> SMEM staging ----------------
    #pragma unroll
    for (int rr = 0; rr < ROWS_PER_WARP; rr++) {
        const int row = row0 + rr;
        const int ci = cls[row];
        cls_r[rr] = ci;
        int k = 0;
        if (!(ci >= 24 && ci <= 26)) {
            const int bi = batch[row];
            const int lo = lower_bound_dev(batch, N, bi);
            const int hi = upper_bound_dev(batch, N, bi);
            const float4 a  = reinterpret_cast<const float4*>(z1 + (size_t)row * 128)[lane];
            const float4 zv = make_float4(0.f, 0.f, 0.f, 0.f);

            for (int jb = lo; jb < hi; jb += 32) {
                const int j = jb + lane;
                const bool p = (j < hi) && (j != row) && (cls[j] == ci);
                unsigned m = __ballot_sync(0xffffffffu, p);
                while (m) {
                    // peel up to 4 matches -> 4 independent load/reduce chains
                    int jj0 = jb + __ffs(m) - 1; m &= m - 1;
                    int jj1 = -1, jj2 = -1, jj3 = -1;
                    if (m) { jj1 = jb + __ffs(m) - 1; m &= m - 1; }
                    if (m) { jj2 = jb + __ffs(m) - 1; m &= m - 1; }
                    if (m) { jj3 = jb + __ffs(m) - 1; m &= m - 1; }

                    float4 v0 = reinterpret_cast<const float4*>(z2 + (size_t)jj0 * 128)[lane];
                    float4 v1 = (jj1 >= 0) ? reinterpret_cast<const float4*>(z2 + (size_t)jj1 * 128)[lane] : zv;
                    float4 v2 = (jj2 >= 0) ? reinterpret_cast<const float4*>(z2 + (size_t)jj2 * 128)[lane] : zv;
                    float4 v3 = (jj3 >= 0) ? reinterpret_cast<const float4*>(z2 + (size_t)jj3 * 128)[lane] : zv;

                    float d0 = a.x * v0.x + a.y * v0.y + a.z * v0.z + a.w * v0.w;
                    float d1 = a.x * v1.x + a.y * v1.y + a.z * v1.z + a.w * v1.w;
                    float d2 = a.x * v2.x + a.y * v2.y + a.z * v2.z + a.w * v2.w;
                    float d3 = a.x * v3.x + a.y * v3.y + a.z * v3.z + a.w * v3.w;

                    d0 = warp_reduce_add(d0);
                    d1 = warp_reduce_add(d1);
                    d2 = warp_reduce_add(d2);
                    d3 = warp_reduce_add(d3);

                    if (lane == 0) {
                        if (k < CAP)                 { scol[w][rr][k]     = jj0; sval[w][rr][k]     = d0; }
                        if (jj1 >= 0 && k + 1 < CAP) { scol[w][rr][k + 1] = jj1; sval[w][rr][k + 1] = d1; }
                        if (jj2 >= 0 && k + 2 < CAP) { scol[w][rr][k + 2] = jj2; sval[w][rr][k + 2] = d2; }
                        if (jj3 >= 0 && k + 3 < CAP) { scol[w][rr][k + 3] = jj3; sval[w][rr][k + 3] = d3; }
                    }
                    k += 1 + (jj1 >= 0) + (jj2 >= 0) + (jj3 >= 0);
                }
            }
        }
        kcnt[rr] = k;
    }
    __syncwarp();

    // ------- phase 2: zero-fill the 2-row contiguous span (pure stores) ----
    {
        float4* span4 = reinterpret_cast<float4*>(out + (size_t)row0 * (size_t)N);
        const int n4 = (N * ROWS_PER_WARP) >> 2;
        const float4 z = make_float4(0.f, 0.f, 0.f, 0.f);
        #pragma unroll 8
        for (int i = lane; i < n4; i += 32) span4[i] = z;
    }
    __syncwarp();   // order fill stores before value overwrites (cross-lane)

    // ---------------- phase 3: overwrite staged values (SMEM only) --------
    #pragma unroll
    for (int rr = 0; rr < ROWS_PER_WARP; rr++) {
        float* orow = out + (size_t)(row0 + rr) * (size_t)N;
        const int kk = min(kcnt[rr], CAP);
        for (int s = lane; s < kk; s += 32)
            orow[scol[w][rr][s]] = sval[w][rr][s];
    }

    // ---------------- overflow slow path (never expected) -----------------
    #pragma unroll
    for (int rr = 0; rr < ROWS_PER_WARP; rr++) {
        if (kcnt[rr] <= CAP) continue;
        const int row = row0 + rr;
        const int ci = cls_r[rr];
        const int bi = batch[row];
        const int lo = lower_bound_dev(batch, N, bi);
        const int hi = upper_bound_dev(batch, N, bi);
        const float4 a = reinterpret_cast<const float4*>(z1 + (size_t)row * 128)[lane];
        float* orow = out + (size_t)row * (size_t)N;
        for (int jb = lo; jb < hi; jb += 32) {
            const int j = jb + lane;
            const bool p = (j < hi) && (j != row) && (cls[j] == ci);
            unsigned m = __ballot_sync(0xffffffffu, p);
            while (m) {
                const int b = __ffs(m) - 1; m &= m - 1;
                const int jj = jb + b;
                const float4 v = reinterpret_cast<const float4*>(z2 + (size_t)jj * 128)[lane];
                float d = a.x * v.x + a.y * v.y + a.z * v.z + a.w * v.w;
                d = warp_reduce_add(d);
                if (lane == 0) orow[jj] = d;
            }
        }
    }
}

// ----------------- generic fallback (any D): memset + direct scatter -------
__global__ void seg_decoder_sparse_generic(const float* __restrict__ z1,
                                           const float* __restrict__ z2,
                                           const int*  __restrict__ cls,
                                           const int*  __restrict__ batch,
                                           float* __restrict__ out,
                                           int N, int D)
{
    const int lane = threadIdx.x & 31;
    const int row  = (blockIdx.x * blockDim.x + threadIdx.x) >> 5;
    if (row >= N) return;

    const int ci = cls[row];
    if (ci >= 24 && ci <= 26) return;
    const int bi = batch[row];
    const int lo = lower_bound_dev(batch, N, bi);
    const int hi = upper_bound_dev(batch, N, bi);
    const float* arow = z1 + (size_t)row * D;
    float* orow = out + (size_t)row * (size_t)N;

    for (int jb = lo; jb < hi; jb += 32) {
        const int j = jb + lane;
        const bool p = (j < hi) && (j != row) && (cls[j] == ci);
        unsigned m = __ballot_sync(0xffffffffu, p);
        while (m) {
            const int b = __ffs(m) - 1; m &= m - 1;
            const int jj = jb + b;
            const float* vrow = z2 + (size_t)jj * D;
            float d = 0.f;
            for (int kk = lane; kk < D; kk += 32) d += arow[kk] * vrow[kk];
            d = warp_reduce_add(d);
            if (lane == 0) orow[jj] = d;
        }
    }
}

extern "C" void kernel_launch(void* const* d_in, const int* in_sizes, int n_in,
                              void* d_out, int out_size)
{
    const float* z1    = (const float*)d_in[0];
    const float* z2    = (const float*)d_in[1];
    const int*   cls   = (const int*)d_in[2];
    const int*   batch = (const int*)d_in[3];
    float*       out   = (float*)d_out;

    const int N = in_sizes[2];
    const int D = in_sizes[0] / N;

    if (D == 128 && (N % (ROWS_PER_WARP * 8)) == 0 && (N & 3) == 0) {
        // one wave: N/2 warps, 8 warps per CTA
        const int ctas = N / (ROWS_PER_WARP * 8);      // 768 for N=12288
        fused_onewave_d128<<<ctas, 256>>>(z1, z2, cls, batch, out, N);
    } else {
        cudaMemsetAsync(out, 0, (size_t)out_size * sizeof(float));
        const int blocks = (N * 32 + 255) / 256;
        seg_decoder_sparse_generic<<<blocks, 256>>>(z1, z2, cls, batch, out, N, D);
    }
}

// round 10
// speedup vs baseline: 1.1071x; 1.1071x over previous
#include <cuda_runtime.h>
#include <cuda_bf16.h>

// out[i,j] = dot(z1[i], z2[j]) if batch[i]==batch[j] && cls[i]==cls[j]
//            && !(24<=cls[i]<=26) && i!=j, else 0.
//
// Round-8 structure (best so far), one change: the zero-fill uses streaming
// stores (st.global.cs via __stcs) so 604MB of zeros doesn't write-allocate /
// dirty the whole L2 — the hypothesized reason plain STG streams cap at
// ~5.1TB/s while driver memset hits 7.2TB/s.
//   phase 1: sparse dots -> SMEM staging   (clean L2)
//   phase 2: zero-fill row with __stcs     (streaming, evict-first)
//   phase 3: overwrite staged values       (SMEM reads only)

#define CAP 64               // staged matches per row (avg ~9.5; tail-safe)

__device__ __forceinline__ int lower_bound_dev(const int* __restrict__ a, int n, int v) {
    int lo = 0, hi = n;
    while (lo < hi) { int m = (lo + hi) >> 1; if (a[m] < v) lo = m + 1; else hi = m; }
    return lo;
}
__device__ __forceinline__ int upper_bound_dev(const int* __restrict__ a, int n, int v) {
    int lo = 0, hi = n;
    while (lo < hi) { int m = (lo + hi) >> 1; if (a[m] <= v) lo = m + 1; else hi = m; }
    return lo;
}
__device__ __forceinline__ float warp_reduce_add(float d) {
    d += __shfl_xor_sync(0xffffffffu, d, 16);
    d += __shfl_xor_sync(0xffffffffu, d, 8);
    d += __shfl_xor_sync(0xffffffffu, d, 4);
    d += __shfl_xor_sync(0xffffffffu, d, 2);
    d += __shfl_xor_sync(0xffffffffu, d, 1);
    return d;
}

__global__ void __launch_bounds__(256)
fused_sparse_then_fill_cs_d128(const float* __restrict__ z1,
                               const float* __restrict__ z2,
                               const int*  __restrict__ cls,
                               const int*  __restrict__ batch,
                               float* __restrict__ out,
                               int N)
{
    __shared__ int   scol[8][CAP];   // 8 warps per block
    __shared__ float sval[8][CAP];

    const int lane = threadIdx.x & 31;
    const int w    = threadIdx.x >> 5;
    const int row  = (blockIdx.x * blockDim.x + threadIdx.x) >> 5;
    if (row >= N) return;

    // ---------------- phase 1: sparse dots -> SMEM staging ----------------
    int k = 0;                         // uniform across the warp
    const int ci = cls[row];
    if (!(ci >= 24 && ci <= 26)) {
        const int bi = batch[row];
        const int lo = lower_bound_dev(batch, N, bi);
        const int hi = upper_bound_dev(batch, N, bi);
        const float4 a  = reinterpret_cast<const float4*>(z1 + (size_t)row * 128)[lane];
        const float4 zv = make_float4(0.f, 0.f, 0.f, 0.f);

        for (int jb = lo; jb < hi; jb += 32) {
            const int j = jb + lane;
            const bool p = (j < hi) && (j != row) && (cls[j] == ci);
            unsigned m = __ballot_sync(0xffffffffu, p);
            while (m) {
                // peel up to 4 matches -> 4 independent load/reduce chains
                int jj0 = jb + __ffs(m) - 1; m &= m - 1;
                int jj1 = -1, jj2 = -1, jj3 = -1;
                if (m) { jj1 = jb + __ffs(m) - 1; m &= m - 1; }
                if (m) { jj2 = jb + __ffs(m) - 1; m &= m - 1; }
                if (m) { jj3 = jb + __ffs(m) - 1; m &= m - 1; }

                float4 v0 = reinterpret_cast<const float4*>(z2 + (size_t)jj0 * 128)[lane];
                float4 v1 = (jj1 >= 0) ? reinterpret_cast<const float4*>(z2 + (size_t)jj1 * 128)[lane] : zv;
                float4 v2 = (jj2 >= 0) ? reinterpret_cast<const float4*>(z2 + (size_t)jj2 * 128)[lane] : zv;
                float4 v3 = (jj3 >= 0) ? reinterpret_cast<const float4*>(z2 + (size_t)jj3 * 128)[lane] : zv;

                float d0 = a.x * v0.x + a.y * v0.y + a.z * v0.z + a.w * v0.w;
                float d1 = a.x * v1.x + a.y * v1.y + a.z * v1.z + a.w * v1.w;
                float d2 = a.x * v2.x + a.y * v2.y + a.z * v2.z + a.w * v2.w;
                float d3 = a.x * v3.x + a.y * v3.y + a.z * v3.z + a.w * v3.w;

                d0 = warp_reduce_add(d0);
                d1 = warp_reduce_add(d1);
                d2 = warp_reduce_add(d2);
                d3 = warp_reduce_add(d3);

                if (lane == 0) {
                    if (k < CAP)                 { scol[w][k]     = jj0; sval[w][k]     = d0; }
                    if (jj1 >= 0 && k + 1 < CAP) { scol[w][k + 1] = jj1; sval[w][k + 1] = d1; }
                    if (jj2 >= 0 && k + 2 < CAP) { scol[w][k + 2] = jj2; sval[w][k + 2] = d2; }
                    if (jj3 >= 0 && k + 3 < CAP) { scol[w][k + 3] = jj3; sval[w][k + 3] = d3; }
                }
                k += 1 + (jj1 >= 0) + (jj2 >= 0) + (jj3 >= 0);
            }
        }
    }
    __syncwarp();   // staging visible warp-wide before fill

    // ------ phase 2: zero-fill this row with STREAMING stores (st.cs) ------
    {
        float4* orow4 = reinterpret_cast<float4*>(out + (size_t)row * (size_t)N);
        const int n4 = N >> 2;
        const float4 z = make_float4(0.f, 0.f, 0.f, 0.f);
        #pragma unroll 16
        for (int i = lane; i < n4; i += 32)
            __stcs(orow4 + i, z);           // evict-first: don't dirty L2
    }
    __syncwarp();   // order fill stores before value overwrites (cross-lane)

    // ---------------- phase 3: overwrite staged values (SMEM only) --------
    float* orow = out + (size_t)row * (size_t)N;
    const int kk = min(k, CAP);
    for (int s = lane; s < kk; s += 32)
        orow[scol[w][s]] = sval[w][s];

    // ---------------- overflow slow path (never expected) -----------------
    if (k > CAP) {
        const int bi = batch[row];
        const int lo = lower_bound_dev(batch, N, bi);
        const int hi = upper_bound_dev(batch, N, bi);
        const float4 a = reinterpret_cast<const float4*>(z1 + (size_t)row * 128)[lane];
        for (int jb = lo; jb < hi; jb += 32) {
            const int j = jb + lane;
            const bool p = (j < hi) && (j != row) && (cls[j] == ci);
            unsigned m = __ballot_sync(0xffffffffu, p);
            while (m) {
                const int b = __ffs(m) - 1; m &= m - 1;
                const int jj = jb + b;
                const float4 v = reinterpret_cast<const float4*>(z2 + (size_t)jj * 128)[lane];
                float d = a.x * v.x + a.y * v.y + a.z * v.z + a.w * v.w;
                d = warp_reduce_add(d);
                if (lane == 0) orow[jj] = d;
            }
        }
    }
}

// ----------------- generic fallback (any D): memset + direct scatter -------
__global__ void seg_decoder_sparse_generic(const float* __restrict__ z1,
                                           const float* __restrict__ z2,
                                           const int*  __restrict__ cls,
                                           const int*  __restrict__ batch,
                                           float* __restrict__ out,
                                           int N, int D)
{
    const int lane = threadIdx.x & 31;
    const int row  = (blockIdx.x * blockDim.x + threadIdx.x) >> 5;
    if (row >= N) return;

    const int ci = cls[row];
    if (ci >= 24 && ci <= 26) return;
    const int bi = batch[row];
    const int lo = lower_bound_dev(batch, N, bi);
    const int hi = upper_bound_dev(batch, N, bi);
    const float* arow = z1 + (size_t)row * D;
    float* orow = out + (size_t)row * (size_t)N;

    for (int jb = lo; jb < hi; jb += 32) {
        const int j = jb + lane;
        const bool p = (j < hi) && (j != row) && (cls[j] == ci);
        unsigned m = __ballot_sync(0xffffffffu, p);
        while (m) {
            const int b = __ffs(m) - 1; m &= m - 1;
            const int jj = jb + b;
            const float* vrow = z2 + (size_t)jj * D;
            float d = 0.f;
            for (int kk = lane; kk < D; kk += 32) d += arow[kk] * vrow[kk];
            d = warp_reduce_add(d);
            if (lane == 0) orow[jj] = d;
        }
    }
}

extern "C" void kernel_launch(void* const* d_in, const int* in_sizes, int n_in,
                              void* d_out, int out_size)
{
    const float* z1    = (const float*)d_in[0];
    const float* z2    = (const float*)d_in[1];
    const int*   cls   = (const int*)d_in[2];
    const int*   batch = (const int*)d_in[3];
    float*       out   = (float*)d_out;

    const int N = in_sizes[2];
    const int D = in_sizes[0] / N;

    if (D == 128 && (N & 3) == 0) {
        const int blocks = (N * 32 + 255) / 256;   // one warp per row
        fused_sparse_then_fill_cs_d128<<<blocks, 256>>>(z1, z2, cls, batch, out, N);
    } else {
        cudaMemsetAsync(out, 0, (size_t)out_size * sizeof(float));
        const int blocks = (N * 32 + 255) / 256;
        seg_decoder_sparse_generic<<<blocks, 256>>>(z1, z2, cls, batch, out, N, D);
    }
}